// round 1
// baseline (speedup 1.0000x reference)
#include <cuda_runtime.h>
#include <cstdint>

#define HW   16384
#define CCH  256
#define EPSF 1e-8f

#define BM 128
#define BN 128
#define BK 8

// ---------------- scratch (no allocations allowed) ----------------
__device__ float              g_inv_nb[HW];   // 1/(sqrt(ssb+eps)+eps)  (argmax scale)
__device__ float              g_bn[HW];       // sqrt(ssb) exact        (final tn)
__device__ float              g_an[HW];       // sqrt(ssa) exact        (final an)
__device__ unsigned long long g_best[HW];     // packed (mono(val)<<32 | ~q)
__device__ float              g_partial[64];

// ---------------- f32x2 helpers (Blackwell packed fp32) ----------------
__device__ __forceinline__ unsigned long long ffma2(unsigned long long x,
                                                    unsigned long long y,
                                                    unsigned long long z) {
    unsigned long long d;
    asm("fma.rn.f32x2 %0, %1, %2, %3;" : "=l"(d) : "l"(x), "l"(y), "l"(z));
    return d;
}
__device__ __forceinline__ unsigned long long pack2_dup(float v) {
    unsigned long long d;
    unsigned u = __float_as_uint(v);
    asm("mov.b64 %0, {%1, %1};" : "=l"(d) : "r"(u));
    return d;
}
__device__ __forceinline__ void unpack2(unsigned long long v, float& lo, float& hi) {
    unsigned a, b;
    asm("mov.b64 {%0, %1}, %2;" : "=r"(a), "=r"(b) : "l"(v));
    lo = __uint_as_float(a);
    hi = __uint_as_float(b);
}

// ---------------- kernel 1: column norms + init ----------------
__global__ void k_norms(const float* __restrict__ a, const float* __restrict__ b) {
    int idx = blockIdx.x * blockDim.x + threadIdx.x;   // 0..32767
    if (idx < HW) {
        float ss = 0.f;
        #pragma unroll 8
        for (int c = 0; c < CCH; ++c) {
            float v = b[c * HW + idx];
            ss = fmaf(v, v, ss);
        }
        g_inv_nb[idx] = 1.f / (sqrtf(ss + EPSF) + EPSF);
        g_bn[idx]     = sqrtf(ss);
        g_best[idx]   = 0ULL;   // below any real key (mono >= 0, idx-part > 0)
    } else {
        int p = idx - HW;
        float ss = 0.f;
        #pragma unroll 8
        for (int c = 0; c < CCH; ++c) {
            float v = a[c * HW + p];
            ss = fmaf(v, v, ss);
        }
        g_an[p] = sqrtf(ss);
    }
}

// ---------------- kernel 2: fused GEMM (S = A^T B) + scaled row-argmax ----------------
// A, B are [C, HW] row-major (K-major for both operands -> classic TN SGEMM).
__global__ void __launch_bounds__(256, 2)
k_gemm_argmax(const float* __restrict__ A, const float* __restrict__ B) {
    __shared__ __align__(16) float As[BK][BM];
    __shared__ __align__(16) float Bs[BK][BN];

    const int bm  = blockIdx.y * BM;        // p offset
    const int bn  = blockIdx.x * BN;        // q offset
    const int tid = threadIdx.x;

    const int lk = tid >> 5;                // 0..7   (k row of the load)
    const int lm = (tid & 31) << 2;         // 0..124 (float4 column)
    const int tx = tid & 15;                // 0..15  (q sub-tile)
    const int ty = tid >> 4;                // 0..15  (p sub-tile)

    const float* Ald = A + (size_t)lk * HW + bm + lm;
    const float* Bld = B + (size_t)lk * HW + bn + lm;

    // 8 rows x 4 column-pairs of packed fp32 accumulators
    unsigned long long acc[8][4];
    #pragma unroll
    for (int i = 0; i < 8; ++i)
        #pragma unroll
        for (int j = 0; j < 4; ++j) acc[i][j] = 0ULL;

    float4 ra = *(const float4*)Ald;
    float4 rb = *(const float4*)Bld;

    for (int k0 = 0; k0 < CCH; k0 += BK) {
        *(float4*)&As[lk][lm] = ra;
        *(float4*)&Bs[lk][lm] = rb;
        __syncthreads();

        if (k0 + BK < CCH) {
            ra = *(const float4*)(Ald + (size_t)(k0 + BK) * HW);
            rb = *(const float4*)(Bld + (size_t)(k0 + BK) * HW);
        }

        #pragma unroll
        for (int kk = 0; kk < BK; ++kk) {
            float4 a0 = *(const float4*)&As[kk][ty * 8];
            float4 a1 = *(const float4*)&As[kk][ty * 8 + 4];
            // B pairs read directly as packed 64-bit lanes (lo = even q)
            ulonglong2 q0 = *(const ulonglong2*)&Bs[kk][tx * 8];
            ulonglong2 q1 = *(const ulonglong2*)&Bs[kk][tx * 8 + 4];
            unsigned long long bp0 = q0.x, bp1 = q0.y, bp2 = q1.x, bp3 = q1.y;

            unsigned long long ad[8];
            ad[0] = pack2_dup(a0.x); ad[1] = pack2_dup(a0.y);
            ad[2] = pack2_dup(a0.z); ad[3] = pack2_dup(a0.w);
            ad[4] = pack2_dup(a1.x); ad[5] = pack2_dup(a1.y);
            ad[6] = pack2_dup(a1.z); ad[7] = pack2_dup(a1.w);

            #pragma unroll
            for (int i = 0; i < 8; ++i) {
                acc[i][0] = ffma2(ad[i], bp0, acc[i][0]);
                acc[i][1] = ffma2(ad[i], bp1, acc[i][1]);
                acc[i][2] = ffma2(ad[i], bp2, acc[i][2]);
                acc[i][3] = ffma2(ad[i], bp3, acc[i][3]);
            }
        }
        __syncthreads();
    }

    // ---- epilogue: scale by 1/nb_q, per-row argmax, cross-lane + global max ----
    float inv[8];
    #pragma unroll
    for (int j = 0; j < 8; ++j) inv[j] = g_inv_nb[bn + tx * 8 + j];

    #pragma unroll
    for (int i = 0; i < 8; ++i) {
        float bestv = -3.402823e38f;
        int   bj    = 0;
        #pragma unroll
        for (int j2 = 0; j2 < 4; ++j2) {
            float lo, hi;
            unpack2(acc[i][j2], lo, hi);
            float v0 = lo * inv[j2 * 2];
            float v1 = hi * inv[j2 * 2 + 1];
            if (v0 > bestv) { bestv = v0; bj = j2 * 2; }
            if (v1 > bestv) { bestv = v1; bj = j2 * 2 + 1; }
        }
        // monotonic float->uint encoding; tie-break = smaller q (matches jnp.argmin)
        unsigned u = __float_as_uint(bestv);
        u = (u & 0x80000000u) ? ~u : (u | 0x80000000u);
        unsigned q = (unsigned)(bn + tx * 8 + bj);
        unsigned long long key =
            ((unsigned long long)u << 32) | (unsigned long long)(0xFFFFFFFFu - q);

        // reduce over the 16 lanes sharing this row (same ty -> contiguous 16 lanes)
        #pragma unroll
        for (int m = 8; m >= 1; m >>= 1) {
            unsigned long long o = __shfl_xor_sync(0xFFFFFFFFu, key, m);
            if (o > key) key = o;
        }
        if (tx == 0) atomicMax(&g_best[bm + ty * 8 + i], key);
    }
}

// ---------------- kernel 3: gather matched column, exact cosine, block partials ----------------
__global__ void k_loss(const float* __restrict__ a, const float* __restrict__ b) {
    int p = blockIdx.x * blockDim.x + threadIdx.x;   // 0..16383
    unsigned long long key = g_best[p];
    int q = (int)(0xFFFFFFFFu - (unsigned)(key & 0xFFFFFFFFull));

    float dot = 0.f;
    #pragma unroll 8
    for (int c = 0; c < CCH; ++c)
        dot = fmaf(a[c * HW + p], b[c * HW + q], dot);

    float cs  = dot / ((g_an[p] + EPSF) * (g_bn[q] + EPSF));
    float val = 1.f - cs;

    __shared__ float sred[256];
    int t = threadIdx.x;
    sred[t] = val;
    __syncthreads();
    #pragma unroll
    for (int s = 128; s >= 1; s >>= 1) {
        if (t < s) sred[t] += sred[t + s];
        __syncthreads();
    }
    if (t == 0) g_partial[blockIdx.x] = sred[0];
}

// ---------------- kernel 4: deterministic final reduce ----------------
__global__ void k_final(float* __restrict__ out) {
    __shared__ float s[64];
    int t = threadIdx.x;
    s[t] = g_partial[t];
    __syncthreads();
    #pragma unroll
    for (int st = 32; st >= 1; st >>= 1) {
        if (t < st) s[t] += s[t + st];
        __syncthreads();
    }
    if (t == 0) out[0] = s[0] / (float)HW;
}

// ---------------- launch ----------------
extern "C" void kernel_launch(void* const* d_in, const int* in_sizes, int n_in,
                              void* d_out, int out_size) {
    const float* a = (const float*)d_in[0];
    const float* b = (const float*)d_in[1];
    float* out = (float*)d_out;

    k_norms<<<128, 256>>>(a, b);
    dim3 grid(HW / BN, HW / BM);
    k_gemm_argmax<<<grid, 256>>>(a, b);
    k_loss<<<HW / 256, 256>>>(a, b);
    k_final<<<1, 64>>>(out);
}

// round 3
// speedup vs baseline: 5.3992x; 5.3992x over previous
#include <cuda_runtime.h>
#include <cstdint>

#define HW   16384
#define CCH  256
#define EPSF 1e-8f

// ---------------- scratch (no allocations allowed) ----------------
__device__ float              g_inv_nb[HW];
__device__ float              g_bn[HW];
__device__ float              g_an[HW];
__device__ unsigned long long g_best[HW];
__device__ float              g_partial[64];
__device__ unsigned int       g_at[HW * CCH];   // tf32 bits, [p][c] K-major, 16MB
__device__ unsigned int       g_bt[HW * CCH];   // tf32 bits, [q][c] K-major, 16MB

// ---------------- helpers ----------------
__device__ __forceinline__ uint32_t smem_to_u32(const void* p) {
    uint32_t a;
    asm("{ .reg .u64 t; cvta.to.shared.u64 t, %1; cvt.u32.u64 %0, t; }" : "=r"(a) : "l"(p));
    return a;
}
__device__ __forceinline__ void cp16(uint32_t dst, const void* src) {
    asm volatile("cp.async.ca.shared.global [%0], [%1], 16;" :: "r"(dst), "l"(src) : "memory");
}
__device__ __forceinline__ void mma_tf32(float* d, const uint32_t* a, const uint32_t* b) {
    asm volatile(
        "mma.sync.aligned.m16n8k8.row.col.f32.tf32.tf32.f32 "
        "{%0,%1,%2,%3}, {%4,%5,%6,%7}, {%8,%9}, {%0,%1,%2,%3};"
        : "+f"(d[0]), "+f"(d[1]), "+f"(d[2]), "+f"(d[3])
        : "r"(a[0]), "r"(a[1]), "r"(a[2]), "r"(a[3]), "r"(b[0]), "r"(b[1]));
}

// smem layout (dynamic): stages of A(16KB)+B(16KB), double buffered, + inv
static constexpr int OFF_A0 = 0;
static constexpr int OFF_B0 = 16384;
static constexpr int OFF_A1 = 32768;
static constexpr int OFF_B1 = 49152;
static constexpr int OFF_INV = 65536;
static constexpr int SMEM_BYTES = 65536 + 1024;

// ---------------- kernel 0: fp32 [C,HW] -> tf32(rounded) [HW,C] transpose ----------------
__global__ void k_cvt(const float* __restrict__ a, const float* __restrict__ b) {
    __shared__ float t[32][33];
    const float*  src = blockIdx.z ? b : a;
    unsigned int* dst = blockIdx.z ? g_bt : g_at;
    int p0 = blockIdx.x * 32, c0 = blockIdx.y * 32;
    int tx = threadIdx.x, ty = threadIdx.y;   // 32 x 8
    #pragma unroll
    for (int i = 0; i < 4; ++i)
        t[ty + i * 8][tx] = src[(size_t)(c0 + ty + i * 8) * HW + p0 + tx];
    __syncthreads();
    #pragma unroll
    for (int i = 0; i < 4; ++i) {
        float v = t[tx][ty + i * 8];
        unsigned int o;
        asm("cvt.rn.tf32.f32 %0, %1;" : "=r"(o) : "f"(v));
        dst[(size_t)(p0 + ty + i * 8) * CCH + c0 + tx] = o;
    }
}

// ---------------- kernel 1: column norms + init ----------------
__global__ void k_norms(const float* __restrict__ a, const float* __restrict__ b) {
    int idx = blockIdx.x * blockDim.x + threadIdx.x;
    if (idx < HW) {
        float ss = 0.f;
        #pragma unroll 8
        for (int c = 0; c < CCH; ++c) { float v = b[c * HW + idx]; ss = fmaf(v, v, ss); }
        g_inv_nb[idx] = 1.f / (sqrtf(ss + EPSF) + EPSF);
        g_bn[idx]     = sqrtf(ss);
        g_best[idx]   = 0ULL;
    } else {
        int p = idx - HW;
        float ss = 0.f;
        #pragma unroll 8
        for (int c = 0; c < CCH; ++c) { float v = a[c * HW + p]; ss = fmaf(v, v, ss); }
        g_an[p] = sqrtf(ss);
    }
}

// ---------------- kernel 2: mma.sync tf32 GEMM + scaled row-argmax ----------------
__device__ __forceinline__ void load_stage(uint32_t smb, int offA, int offB,
                                           int bm, int bn, int s, int tid) {
    #pragma unroll
    for (int i = 0; i < 4; ++i) {
        int f4  = tid + i * 256;
        int row = f4 >> 3, k4 = f4 & 7;
        uint32_t d = smb + offA + row * 128 + ((k4 ^ (row & 7)) << 4);
        cp16(d, g_at + (size_t)(bm + row) * CCH + s * 32 + k4 * 4);
    }
    #pragma unroll
    for (int i = 0; i < 4; ++i) {
        int f4  = tid + i * 256;
        int row = f4 >> 3, k4 = f4 & 7;
        uint32_t d = smb + offB + row * 128 + ((k4 ^ (row & 7)) << 4);
        cp16(d, g_bt + (size_t)(bn + row) * CCH + s * 32 + k4 * 4);
    }
}

__global__ void __launch_bounds__(256, 2)
k_gemm() {
    extern __shared__ __align__(1024) char sm[];
    const uint32_t smb = smem_to_u32(sm);
    const int tid  = threadIdx.x;
    const int lane = tid & 31;
    const int wid  = tid >> 5;
    const int wm   = wid & 3;     // 4 warps along M (32 rows each)
    const int wn   = wid >> 2;    // 2 warps along N (64 cols each)
    const int g    = lane >> 2;   // groupID 0..7
    const int tig  = lane & 3;    // thread-in-group

    const int bm = blockIdx.x * 128;   // M fast -> wave shares B tile, A stays in L2
    const int bn = blockIdx.y * 128;

    float* inv_s = (float*)(sm + OFF_INV);
    if (tid < 128) inv_s[tid] = g_inv_nb[bn + tid];

    // loop-invariant swizzled k offsets (r7 == g for all fragment rows)
    uint32_t kOff[8];
    #pragma unroll
    for (int j = 0; j < 8; ++j) kOff[j] = ((uint32_t)(j ^ g) << 4) + tig * 4;

    const int aR0 = (wm * 32 + g) * 128;   // byte offset of a0 row, mt=0
    const int bR0 = (wn * 64 + g) * 128;   // byte offset of b row, nt=0

    float acc[2][8][4];
    #pragma unroll
    for (int mt = 0; mt < 2; ++mt)
        #pragma unroll
        for (int nt = 0; nt < 8; ++nt)
            #pragma unroll
            for (int c = 0; c < 4; ++c) acc[mt][nt][c] = 0.f;

    load_stage(smb, OFF_A0, OFF_B0, bm, bn, 0, tid);
    asm volatile("cp.async.commit_group;" ::: "memory");

    #pragma unroll 2
    for (int s = 0; s < 8; ++s) {
        if (s < 7) {
            load_stage(smb, (s & 1) ? OFF_A0 : OFF_A1, (s & 1) ? OFF_B0 : OFF_B1,
                       bm, bn, s + 1, tid);
            asm volatile("cp.async.commit_group;" ::: "memory");
            asm volatile("cp.async.wait_group 1;" ::: "memory");
        } else {
            asm volatile("cp.async.wait_group 0;" ::: "memory");
        }
        __syncthreads();

        const char* bufA = sm + ((s & 1) ? OFF_A1 : OFF_A0);
        const char* bufB = sm + ((s & 1) ? OFF_B1 : OFF_B0);

        #pragma unroll
        for (int kk = 0; kk < 4; ++kk) {
            uint32_t afr[2][4];
            #pragma unroll
            for (int mt = 0; mt < 2; ++mt) {
                const char* base = bufA + aR0 + mt * 2048;
                afr[mt][0] = *(const uint32_t*)(base +        kOff[2 * kk]);
                afr[mt][1] = *(const uint32_t*)(base + 1024 + kOff[2 * kk]);
                afr[mt][2] = *(const uint32_t*)(base +        kOff[2 * kk + 1]);
                afr[mt][3] = *(const uint32_t*)(base + 1024 + kOff[2 * kk + 1]);
            }
            #pragma unroll
            for (int nt = 0; nt < 8; ++nt) {
                uint32_t bfr[2];
                const char* bb = bufB + bR0 + nt * 1024;
                bfr[0] = *(const uint32_t*)(bb + kOff[2 * kk]);
                bfr[1] = *(const uint32_t*)(bb + kOff[2 * kk + 1]);
                mma_tf32(acc[0][nt], afr[0], bfr);
                mma_tf32(acc[1][nt], afr[1], bfr);
            }
        }
        __syncthreads();
    }

    // ---- epilogue: scale by 1/nb, per-row argmax, lane reduce, global atomicMax ----
    float invE[8], invO[8];
    #pragma unroll
    for (int nt = 0; nt < 8; ++nt) {
        int c0 = wn * 64 + nt * 8 + 2 * tig;
        invE[nt] = inv_s[c0];
        invO[nt] = inv_s[c0 + 1];
    }

    #pragma unroll
    for (int mt = 0; mt < 2; ++mt) {
        #pragma unroll
        for (int half = 0; half < 2; ++half) {
            float bestv = -3.402823e38f;
            int   bcol  = 0;
            #pragma unroll
            for (int nt = 0; nt < 8; ++nt) {
                int   c0 = wn * 64 + nt * 8 + 2 * tig;
                float v0 = acc[mt][nt][half * 2]     * invE[nt];
                float v1 = acc[mt][nt][half * 2 + 1] * invO[nt];
                if (v0 > bestv) { bestv = v0; bcol = c0; }
                if (v1 > bestv) { bestv = v1; bcol = c0 + 1; }
            }
            unsigned u = __float_as_uint(bestv);
            u = (u & 0x80000000u) ? ~u : (u | 0x80000000u);
            unsigned q = (unsigned)(bn + bcol);
            unsigned long long key =
                ((unsigned long long)u << 32) | (unsigned long long)(0xFFFFFFFFu - q);

            unsigned long long o = __shfl_xor_sync(0xFFFFFFFFu, key, 1);
            if (o > key) key = o;
            o = __shfl_xor_sync(0xFFFFFFFFu, key, 2);
            if (o > key) key = o;

            if (tig == 0) {
                int row = bm + wm * 32 + mt * 16 + g + half * 8;
                atomicMax(&g_best[row], key);
            }
        }
    }
}

// ---------------- kernel 3: gather matched column, exact cosine ----------------
__global__ void k_loss(const float* __restrict__ a, const float* __restrict__ b) {
    int p = blockIdx.x * blockDim.x + threadIdx.x;
    unsigned long long key = g_best[p];
    int q = (int)(0xFFFFFFFFu - (unsigned)(key & 0xFFFFFFFFull));

    float dot = 0.f;
    #pragma unroll 8
    for (int c = 0; c < CCH; ++c)
        dot = fmaf(a[c * HW + p], b[c * HW + q], dot);

    float cs  = dot / ((g_an[p] + EPSF) * (g_bn[q] + EPSF));
    float val = 1.f - cs;

    __shared__ float sred[256];
    int t = threadIdx.x;
    sred[t] = val;
    __syncthreads();
    #pragma unroll
    for (int s = 128; s >= 1; s >>= 1) {
        if (t < s) sred[t] += sred[t + s];
        __syncthreads();
    }
    if (t == 0) g_partial[blockIdx.x] = sred[0];
}

__global__ void k_final(float* __restrict__ out) {
    __shared__ float s[64];
    int t = threadIdx.x;
    s[t] = g_partial[t];
    __syncthreads();
    #pragma unroll
    for (int st = 32; st >= 1; st >>= 1) {
        if (t < st) s[t] += s[t + st];
        __syncthreads();
    }
    if (t == 0) out[0] = s[0] / (float)HW;
}

// ---------------- launch ----------------
extern "C" void kernel_launch(void* const* d_in, const int* in_sizes, int n_in,
                              void* d_out, int out_size) {
    const float* a = (const float*)d_in[0];
    const float* b = (const float*)d_in[1];
    float* out = (float*)d_out;

    cudaFuncSetAttribute(k_gemm, cudaFuncAttributeMaxDynamicSharedMemorySize, SMEM_BYTES);

    k_cvt<<<dim3(HW / 32, CCH / 32, 2), dim3(32, 8)>>>(a, b);
    k_norms<<<128, 256>>>(a, b);
    k_gemm<<<dim3(HW / 128, HW / 128), 256, SMEM_BYTES>>>();
    k_loss<<<HW / 256, 256>>>(a, b);
    k_final<<<1, 64>>>(out);
}

// round 4
// speedup vs baseline: 6.1391x; 1.1370x over previous
#include <cuda_runtime.h>
#include <cstdint>

#define HW   16384
#define CCH  256
#define EPSF 1e-8f

// ---------------- scratch (no allocations allowed) ----------------
__device__ float              g_inv_nb[HW];
__device__ float              g_bn[HW];
__device__ float              g_an[HW];
__device__ unsigned long long g_best[HW];
__device__ float              g_partial[512];
__device__ unsigned int       g_at[HW * CCH];   // tf32 bits, [p][c] K-major, 16MB
__device__ unsigned int       g_bt[HW * CCH];   // tf32 bits, [q][c] K-major, 16MB

// ---------------- helpers ----------------
__device__ __forceinline__ uint32_t smem_to_u32(const void* p) {
    uint32_t a;
    asm("{ .reg .u64 t; cvta.to.shared.u64 t, %1; cvt.u32.u64 %0, t; }" : "=r"(a) : "l"(p));
    return a;
}
__device__ __forceinline__ void cp16(uint32_t dst, const void* src) {
    asm volatile("cp.async.ca.shared.global [%0], [%1], 16;" :: "r"(dst), "l"(src) : "memory");
}
__device__ __forceinline__ void mma_tf32(float* d, const uint32_t* a, const uint32_t* b) {
    asm volatile(
        "mma.sync.aligned.m16n8k8.row.col.f32.tf32.tf32.f32 "
        "{%0,%1,%2,%3}, {%4,%5,%6,%7}, {%8,%9}, {%0,%1,%2,%3};"
        : "+f"(d[0]), "+f"(d[1]), "+f"(d[2]), "+f"(d[3])
        : "r"(a[0]), "r"(a[1]), "r"(a[2]), "r"(a[3]), "r"(b[0]), "r"(b[1]));
}
__device__ __forceinline__ void ldsm4(uint32_t* r, uint32_t addr) {
    asm volatile("ldmatrix.sync.aligned.m8n8.x4.shared.b16 {%0,%1,%2,%3}, [%4];"
                 : "=r"(r[0]), "=r"(r[1]), "=r"(r[2]), "=r"(r[3]) : "r"(addr));
}

// smem layout (dynamic): stages of A(16KB)+B(16KB), double buffered, + inv
static constexpr int OFF_A0 = 0;
static constexpr int OFF_B0 = 16384;
static constexpr int OFF_A1 = 32768;
static constexpr int OFF_B1 = 49152;
static constexpr int OFF_INV = 65536;
static constexpr int SMEM_BYTES = 65536 + 1024;

// ---------------- kernel 0: fp32 [C,HW] -> tf32(rounded) [HW,C] transpose ----------------
__global__ void k_cvt(const float* __restrict__ a, const float* __restrict__ b) {
    __shared__ float t[32][33];
    const float*  src = blockIdx.z ? b : a;
    unsigned int* dst = blockIdx.z ? g_bt : g_at;
    int p0 = blockIdx.x * 32, c0 = blockIdx.y * 32;
    int tx = threadIdx.x, ty = threadIdx.y;   // 32 x 8
    #pragma unroll
    for (int i = 0; i < 4; ++i)
        t[ty + i * 8][tx] = src[(size_t)(c0 + ty + i * 8) * HW + p0 + tx];
    __syncthreads();
    #pragma unroll
    for (int i = 0; i < 4; ++i) {
        float v = t[tx][ty + i * 8];
        unsigned int o;
        asm("cvt.rn.tf32.f32 %0, %1;" : "=r"(o) : "f"(v));
        dst[(size_t)(p0 + ty + i * 8) * CCH + c0 + tx] = o;
    }
}

// ---------------- kernel 1: column norms + init ----------------
__global__ void k_norms(const float* __restrict__ a, const float* __restrict__ b) {
    int idx = blockIdx.x * blockDim.x + threadIdx.x;
    if (idx < HW) {
        float ss = 0.f;
        #pragma unroll 8
        for (int c = 0; c < CCH; ++c) { float v = b[c * HW + idx]; ss = fmaf(v, v, ss); }
        g_inv_nb[idx] = 1.f / (sqrtf(ss + EPSF) + EPSF);
        g_bn[idx]     = sqrtf(ss);
        g_best[idx]   = 0ULL;
    } else {
        int p = idx - HW;
        float ss = 0.f;
        #pragma unroll 8
        for (int c = 0; c < CCH; ++c) { float v = a[c * HW + p]; ss = fmaf(v, v, ss); }
        g_an[p] = sqrtf(ss);
    }
}

// ---------------- kernel 2: mma.sync tf32 GEMM (ldmatrix frags) + scaled row-argmax ----------------
__device__ __forceinline__ void load_stage(uint32_t smb, int offA, int offB,
                                           int bm, int bn, int s, int tid) {
    #pragma unroll
    for (int i = 0; i < 4; ++i) {
        int f4  = tid + i * 256;
        int row = f4 >> 3, k4 = f4 & 7;
        uint32_t d = smb + offA + row * 128 + ((k4 ^ (row & 7)) << 4);
        cp16(d, g_at + (size_t)(bm + row) * CCH + s * 32 + k4 * 4);
    }
    #pragma unroll
    for (int i = 0; i < 4; ++i) {
        int f4  = tid + i * 256;
        int row = f4 >> 3, k4 = f4 & 7;
        uint32_t d = smb + offB + row * 128 + ((k4 ^ (row & 7)) << 4);
        cp16(d, g_bt + (size_t)(bn + row) * CCH + s * 32 + k4 * 4);
    }
}

__global__ void __launch_bounds__(256, 2)
k_gemm() {
    extern __shared__ __align__(1024) char sm[];
    const uint32_t smb = smem_to_u32(sm);
    const int tid  = threadIdx.x;
    const int lane = tid & 31;
    const int wid  = tid >> 5;
    const int wm   = wid & 3;     // 4 warps along M (32 rows each)
    const int wn   = wid >> 2;    // 2 warps along N (64 cols each)
    const int g    = lane >> 2;   // groupID 0..7
    const int tig  = lane & 3;    // thread-in-group

    const int bm = blockIdx.x * 128;   // M fast -> wave shares B tile, A stays in L2
    const int bn = blockIdx.y * 128;

    float* inv_s = (float*)(sm + OFF_INV);
    if (tid < 128) inv_s[tid] = g_inv_nb[bn + tid];

    // ---- ldmatrix per-lane address components ----
    const int t8  = lane >> 3;            // tile index 0..3
    const int jr  = lane & 7;             // row within tile
    // A tiles: t0=(rows0-7,lo) t1=(rows8-15,lo) t2=(rows0-7,hi) t3=(rows8-15,hi)
    const uint32_t aRowTerm = (uint32_t)((wm * 32 + (t8 & 1) * 8 + jr) * 128);
    const uint32_t aSel     = (uint32_t)((t8 >> 1) << 4);     // chunk lo/hi select
    // B tiles: t0=(nt0,lo) t1=(nt0,hi) t2=(nt1,lo) t3=(nt1,hi)
    const uint32_t bRowTerm = (uint32_t)((wn * 64 + (t8 >> 1) * 8 + jr) * 128);
    const uint32_t bSel     = (uint32_t)((t8 & 1) << 4);
    const uint32_t jrx      = (uint32_t)(jr << 4);

    float acc[2][8][4];
    #pragma unroll
    for (int mt = 0; mt < 2; ++mt)
        #pragma unroll
        for (int nt = 0; nt < 8; ++nt)
            #pragma unroll
            for (int c = 0; c < 4; ++c) acc[mt][nt][c] = 0.f;

    load_stage(smb, OFF_A0, OFF_B0, bm, bn, 0, tid);
    asm volatile("cp.async.commit_group;" ::: "memory");

    #pragma unroll 2
    for (int s = 0; s < 8; ++s) {
        if (s < 7) {
            load_stage(smb, (s & 1) ? OFF_A0 : OFF_A1, (s & 1) ? OFF_B0 : OFF_B1,
                       bm, bn, s + 1, tid);
            asm volatile("cp.async.commit_group;" ::: "memory");
            asm volatile("cp.async.wait_group 1;" ::: "memory");
        } else {
            asm volatile("cp.async.wait_group 0;" ::: "memory");
        }
        __syncthreads();

        const uint32_t bufA = smb + ((s & 1) ? OFF_A1 : OFF_A0) + aRowTerm;
        const uint32_t bufB = smb + ((s & 1) ? OFF_B1 : OFF_B0) + bRowTerm;

        #pragma unroll
        for (int kk = 0; kk < 4; ++kk) {
            const uint32_t kx0   = ((uint32_t)(kk << 5)) ^ jrx;   // ((2kk)^jr)<<4
            const uint32_t aKOff = kx0 ^ aSel;
            const uint32_t bKOff = kx0 ^ bSel;

            uint32_t afr[2][4];
            ldsm4(afr[0], bufA + aKOff);
            ldsm4(afr[1], bufA + 2048 + aKOff);

            #pragma unroll
            for (int j = 0; j < 4; ++j) {
                uint32_t bfr[4];
                ldsm4(bfr, bufB + (uint32_t)(j * 2048) + bKOff);
                mma_tf32(acc[0][2 * j],     afr[0], bfr);
                mma_tf32(acc[1][2 * j],     afr[1], bfr);
                mma_tf32(acc[0][2 * j + 1], afr[0], bfr + 2);
                mma_tf32(acc[1][2 * j + 1], afr[1], bfr + 2);
            }
        }
        __syncthreads();
    }

    // ---- epilogue: scale by 1/nb, per-row argmax, lane reduce, global atomicMax ----
    float invE[8], invO[8];
    #pragma unroll
    for (int nt = 0; nt < 8; ++nt) {
        int c0 = wn * 64 + nt * 8 + 2 * tig;
        invE[nt] = inv_s[c0];
        invO[nt] = inv_s[c0 + 1];
    }

    #pragma unroll
    for (int mt = 0; mt < 2; ++mt) {
        #pragma unroll
        for (int half = 0; half < 2; ++half) {
            float bestv = -3.402823e38f;
            int   bcol  = 0;
            #pragma unroll
            for (int nt = 0; nt < 8; ++nt) {
                int   c0 = wn * 64 + nt * 8 + 2 * tig;
                float v0 = acc[mt][nt][half * 2]     * invE[nt];
                float v1 = acc[mt][nt][half * 2 + 1] * invO[nt];
                if (v0 > bestv) { bestv = v0; bcol = c0; }
                if (v1 > bestv) { bestv = v1; bcol = c0 + 1; }
            }
            unsigned u = __float_as_uint(bestv);
            u = (u & 0x80000000u) ? ~u : (u | 0x80000000u);
            unsigned q = (unsigned)(bn + bcol);
            unsigned long long key =
                ((unsigned long long)u << 32) | (unsigned long long)(0xFFFFFFFFu - q);

            unsigned long long o = __shfl_xor_sync(0xFFFFFFFFu, key, 1);
            if (o > key) key = o;
            o = __shfl_xor_sync(0xFFFFFFFFu, key, 2);
            if (o > key) key = o;

            if (tig == 0) {
                int row = bm + wm * 32 + mt * 16 + g + half * 8;
                atomicMax(&g_best[row], key);
            }
        }
    }
}

// ---------------- kernel 3: gather matched column, exact cosine (8 lanes / pixel) ----------------
__global__ void k_loss(const float* __restrict__ a, const float* __restrict__ b) {
    const int tid = threadIdx.x;          // 256
    const int grp = tid >> 3;             // 0..31 : pixel slot
    const int l8  = tid & 7;              // lane within pixel group
    const int p   = blockIdx.x * 32 + grp;

    unsigned long long key = g_best[p];
    int q = (int)(0xFFFFFFFFu - (unsigned)(key & 0xFFFFFFFFull));

    float dot = 0.f;
    const int c0 = l8 * 32;
    #pragma unroll
    for (int i = 0; i < 32; ++i) {
        int c = c0 + i;
        dot = fmaf(a[c * HW + p], b[c * HW + q], dot);
    }
    dot += __shfl_xor_sync(0xFFFFFFFFu, dot, 1);
    dot += __shfl_xor_sync(0xFFFFFFFFu, dot, 2);
    dot += __shfl_xor_sync(0xFFFFFFFFu, dot, 4);

    __shared__ float sred[32];
    if (l8 == 0) {
        float cs = dot / ((g_an[p] + EPSF) * (g_bn[q] + EPSF));
        sred[grp] = 1.f - cs;
    }
    __syncthreads();
    if (tid < 32) {
        float v = sred[tid];
        #pragma unroll
        for (int m = 16; m >= 1; m >>= 1)
            v += __shfl_xor_sync(0xFFFFFFFFu, v, m);
        if (tid == 0) g_partial[blockIdx.x] = v;
    }
}

__global__ void k_final(float* __restrict__ out) {
    __shared__ float s[512];
    int t = threadIdx.x;
    s[t] = g_partial[t];
    __syncthreads();
    #pragma unroll
    for (int st = 256; st >= 1; st >>= 1) {
        if (t < st) s[t] += s[t + st];
        __syncthreads();
    }
    if (t == 0) out[0] = s[0] / (float)HW;
}

// ---------------- launch ----------------
extern "C" void kernel_launch(void* const* d_in, const int* in_sizes, int n_in,
                              void* d_out, int out_size) {
    const float* a = (const float*)d_in[0];
    const float* b = (const float*)d_in[1];
    float* out = (float*)d_out;

    cudaFuncSetAttribute(k_gemm, cudaFuncAttributeMaxDynamicSharedMemorySize, SMEM_BYTES);

    k_cvt<<<dim3(HW / 32, CCH / 32, 2), dim3(32, 8)>>>(a, b);
    k_norms<<<128, 256>>>(a, b);
    k_gemm<<<dim3(HW / 128, HW / 128), 256, SMEM_BYTES>>>();
    k_loss<<<HW / 32, 256>>>(a, b);
    k_final<<<1, 512>>>(out);
}

// round 5
// speedup vs baseline: 11.5234x; 1.8771x over previous
#include <cuda_runtime.h>
#include <cuda_fp16.h>
#include <cstdint>

#define HW   16384
#define CCH  256
#define EPSF 1e-8f

// ---------------- scratch (no allocations allowed) ----------------
__device__ float              g_inv_nb[HW];
__device__ float              g_bn[HW];
__device__ float              g_an[HW];
__device__ unsigned long long g_best[HW];
__device__ float              g_partial[512];
__device__ float              g_pnorm[2][8][HW];   // per-32ch-block partial sumsq
__device__ __half             g_ah[HW * CCH];      // fp16, [p][c] K-major, 8MB
__device__ __half             g_bh[HW * CCH];      // fp16, [q][c] K-major, 8MB

// ---------------- helpers ----------------
__device__ __forceinline__ uint32_t smem_to_u32(const void* p) {
    uint32_t a;
    asm("{ .reg .u64 t; cvta.to.shared.u64 t, %1; cvt.u32.u64 %0, t; }" : "=r"(a) : "l"(p));
    return a;
}
__device__ __forceinline__ void cp16(uint32_t dst, const void* src) {
    asm volatile("cp.async.ca.shared.global [%0], [%1], 16;" :: "r"(dst), "l"(src) : "memory");
}
__device__ __forceinline__ void mma_f16(float* d, const uint32_t* a, const uint32_t* b) {
    asm volatile(
        "mma.sync.aligned.m16n8k16.row.col.f32.f16.f16.f32 "
        "{%0,%1,%2,%3}, {%4,%5,%6,%7}, {%8,%9}, {%0,%1,%2,%3};"
        : "+f"(d[0]), "+f"(d[1]), "+f"(d[2]), "+f"(d[3])
        : "r"(a[0]), "r"(a[1]), "r"(a[2]), "r"(a[3]), "r"(b[0]), "r"(b[1]));
}
__device__ __forceinline__ void ldsm4(uint32_t* r, uint32_t addr) {
    asm volatile("ldmatrix.sync.aligned.m8n8.x4.shared.b16 {%0,%1,%2,%3}, [%4];"
                 : "=r"(r[0]), "=r"(r[1]), "=r"(r[2]), "=r"(r[3]) : "r"(addr));
}

// smem: A stage 128 rows x 64 K fp16 = 16KB (128B rows), B same; double buffered
static constexpr int OFF_A0 = 0;
static constexpr int OFF_B0 = 16384;
static constexpr int OFF_A1 = 32768;
static constexpr int OFF_B1 = 49152;
static constexpr int OFF_INV = 65536;
static constexpr int SMEM_BYTES = 65536 + 512;

// ---------------- kernel 0: fp32 [C,HW] -> fp16 [HW,C] transpose + norm partials ----------------
__global__ void k_cvt(const float* __restrict__ a, const float* __restrict__ b) {
    __shared__ float t[32][33];
    __shared__ float ps[8][33];
    const int z = blockIdx.z;
    const float* src = z ? b : a;
    __half*      dst = z ? g_bh : g_ah;
    int p0 = blockIdx.x * 32, c0 = blockIdx.y * 32;
    int tx = threadIdx.x, ty = threadIdx.y;   // 32 x 8
    #pragma unroll
    for (int i = 0; i < 4; ++i)
        t[ty + i * 8][tx] = src[(size_t)(c0 + ty + i * 8) * HW + p0 + tx];
    __syncthreads();
    // partial sum of squares over this 32-channel block, per pixel tx
    {
        float s = 0.f;
        #pragma unroll
        for (int i = 0; i < 4; ++i) { float v = t[ty + i * 8][tx]; s = fmaf(v, v, s); }
        ps[ty][tx] = s;
    }
    // transposed fp16 write
    #pragma unroll
    for (int i = 0; i < 4; ++i) {
        float v = t[tx][ty + i * 8];
        dst[(size_t)(p0 + ty + i * 8) * CCH + c0 + tx] = __float2half_rn(v);
    }
    __syncthreads();
    if (ty == 0) {
        float s = 0.f;
        #pragma unroll
        for (int j = 0; j < 8; ++j) s += ps[j][tx];
        g_pnorm[z][c0 >> 5][p0 + tx] = s;
    }
}

// ---------------- kernel 1: finish norms + init best ----------------
__global__ void k_finnorm() {
    int idx = blockIdx.x * blockDim.x + threadIdx.x;   // 0..32767
    if (idx < HW) {
        float ss = 0.f;
        #pragma unroll
        for (int cb = 0; cb < 8; ++cb) ss += g_pnorm[1][cb][idx];
        g_inv_nb[idx] = 1.f / (sqrtf(ss + EPSF) + EPSF);
        g_bn[idx]     = sqrtf(ss);
        g_best[idx]   = 0ULL;
    } else {
        int p = idx - HW;
        float ss = 0.f;
        #pragma unroll
        for (int cb = 0; cb < 8; ++cb) ss += g_pnorm[0][cb][p];
        g_an[p] = sqrtf(ss);
    }
}

// ---------------- kernel 2: mma.sync fp16 GEMM (64x64 warp tiles) + scaled argmax ----------------
__device__ __forceinline__ void load_stage(uint32_t smb, int offA, int offB,
                                           int bm, int bn, int s, int tid) {
    #pragma unroll
    for (int i = 0; i < 8; ++i) {
        int idx = tid + i * 128;           // 0..1023
        int row = idx >> 3, seg = idx & 7; // seg = 16B (8 fp16) chunk of K64
        uint32_t d = smb + offA + row * 128 + ((seg ^ (row & 7)) << 4);
        cp16(d, g_ah + (size_t)(bm + row) * CCH + s * 64 + seg * 8);
    }
    #pragma unroll
    for (int i = 0; i < 8; ++i) {
        int idx = tid + i * 128;
        int row = idx >> 3, seg = idx & 7;
        uint32_t d = smb + offB + row * 128 + ((seg ^ (row & 7)) << 4);
        cp16(d, g_bh + (size_t)(bn + row) * CCH + s * 64 + seg * 8);
    }
}

__global__ void __launch_bounds__(128, 2)
k_gemm() {
    extern __shared__ __align__(1024) char sm[];
    const uint32_t smb = smem_to_u32(sm);
    const int tid  = threadIdx.x;
    const int lane = tid & 31;
    const int wid  = tid >> 5;    // 0..3
    const int wm   = wid & 1;     // 2 warps along M (64 rows each)
    const int wn   = wid >> 1;    // 2 warps along N (64 cols each)
    const int g    = lane >> 2;   // groupID 0..7
    const int tig  = lane & 3;    // thread-in-group
    const int t8   = lane >> 3;   // ldmatrix tile index 0..3
    const int jr   = lane & 7;    // row within tile

    const int bm = blockIdx.x * 128;   // M fast -> wave shares B tile, A stays in L2
    const int bn = blockIdx.y * 128;

    float* inv_s = (float*)(sm + OFF_INV);
    inv_s[tid] = g_inv_nb[bn + tid];

    // ldmatrix per-lane address invariants
    // A x4 tiles: t0=(m0+0-7,segLo) t1=(m0+8-15,segLo) t2=(rows,segHi) t3
    const uint32_t aRow = (uint32_t)((wm * 64 + (t8 & 1) * 8 + jr) * 128);
    const uint32_t aSel = (uint32_t)(t8 >> 1);
    // B x4 tiles: t0=(n0-7,segLo) t1=(n0-7,segHi) t2=(n8-15,segLo) t3=(n8-15,segHi)
    const uint32_t bRow = (uint32_t)((wn * 64 + (t8 >> 1) * 8 + jr) * 128);
    const uint32_t bSel = (uint32_t)(t8 & 1);
    const uint32_t jrx  = (uint32_t)jr;

    float acc[4][8][4];
    #pragma unroll
    for (int mt = 0; mt < 4; ++mt)
        #pragma unroll
        for (int nt = 0; nt < 8; ++nt)
            #pragma unroll
            for (int c = 0; c < 4; ++c) acc[mt][nt][c] = 0.f;

    load_stage(smb, OFF_A0, OFF_B0, bm, bn, 0, tid);
    asm volatile("cp.async.commit_group;" ::: "memory");

    #pragma unroll 2
    for (int s = 0; s < 4; ++s) {
        if (s < 3) {
            load_stage(smb, (s & 1) ? OFF_A0 : OFF_A1, (s & 1) ? OFF_B0 : OFF_B1,
                       bm, bn, s + 1, tid);
            asm volatile("cp.async.commit_group;" ::: "memory");
            asm volatile("cp.async.wait_group 1;" ::: "memory");
        } else {
            asm volatile("cp.async.wait_group 0;" ::: "memory");
        }
        __syncthreads();

        const uint32_t bufA = smb + ((s & 1) ? OFF_A1 : OFF_A0) + aRow;
        const uint32_t bufB = smb + ((s & 1) ? OFF_B1 : OFF_B0) + bRow;

        #pragma unroll
        for (int ks = 0; ks < 4; ++ks) {   // k16 steps within K=64 stage
            const uint32_t aOff = ((((uint32_t)(2 * ks) | aSel) ^ jrx) << 4);
            const uint32_t bOff = ((((uint32_t)(2 * ks) | bSel) ^ jrx) << 4);

            uint32_t afr[4][4], bfr[4][4];
            #pragma unroll
            for (int mt = 0; mt < 4; ++mt) ldsm4(afr[mt], bufA + mt * 2048 + aOff);
            #pragma unroll
            for (int bt = 0; bt < 4; ++bt) ldsm4(bfr[bt], bufB + bt * 2048 + bOff);

            #pragma unroll
            for (int mt = 0; mt < 4; ++mt)
                #pragma unroll
                for (int bt = 0; bt < 4; ++bt) {
                    mma_f16(acc[mt][2 * bt],     afr[mt], bfr[bt]);
                    mma_f16(acc[mt][2 * bt + 1], afr[mt], bfr[bt] + 2);
                }
        }
        __syncthreads();
    }

    // ---- epilogue: scale by 1/nb, per-row argmax, lane reduce, global atomicMax ----
    float invE[8], invO[8];
    #pragma unroll
    for (int nt = 0; nt < 8; ++nt) {
        int c0 = wn * 64 + nt * 8 + 2 * tig;
        invE[nt] = inv_s[c0];
        invO[nt] = inv_s[c0 + 1];
    }

    #pragma unroll
    for (int mt = 0; mt < 4; ++mt) {
        #pragma unroll
        for (int half = 0; half < 2; ++half) {
            float bestv = -3.402823e38f;
            int   bcol  = 0;
            #pragma unroll
            for (int nt = 0; nt < 8; ++nt) {
                int   c0 = wn * 64 + nt * 8 + 2 * tig;
                float v0 = acc[mt][nt][half * 2]     * invE[nt];
                float v1 = acc[mt][nt][half * 2 + 1] * invO[nt];
                if (v0 > bestv) { bestv = v0; bcol = c0; }
                if (v1 > bestv) { bestv = v1; bcol = c0 + 1; }
            }
            unsigned u = __float_as_uint(bestv);
            u = (u & 0x80000000u) ? ~u : (u | 0x80000000u);
            unsigned q = (unsigned)(bn + bcol);
            unsigned long long key =
                ((unsigned long long)u << 32) | (unsigned long long)(0xFFFFFFFFu - q);

            unsigned long long o = __shfl_xor_sync(0xFFFFFFFFu, key, 1);
            if (o > key) key = o;
            o = __shfl_xor_sync(0xFFFFFFFFu, key, 2);
            if (o > key) key = o;

            if (tig == 0) {
                int row = bm + wm * 64 + mt * 16 + g + half * 8;
                atomicMax(&g_best[row], key);
            }
        }
    }
}

// ---------------- kernel 3: gather matched column, exact cosine (8 lanes / pixel) ----------------
__global__ void k_loss(const float* __restrict__ a, const float* __restrict__ b) {
    const int tid = threadIdx.x;          // 256
    const int grp = tid >> 3;             // 0..31 : pixel slot
    const int l8  = tid & 7;
    const int p   = blockIdx.x * 32 + grp;

    unsigned long long key = g_best[p];
    int q = (int)(0xFFFFFFFFu - (unsigned)(key & 0xFFFFFFFFull));

    float dot = 0.f;
    const int c0 = l8 * 32;
    #pragma unroll
    for (int i = 0; i < 32; ++i) {
        int c = c0 + i;
        dot = fmaf(a[c * HW + p], b[c * HW + q], dot);
    }
    dot += __shfl_xor_sync(0xFFFFFFFFu, dot, 1);
    dot += __shfl_xor_sync(0xFFFFFFFFu, dot, 2);
    dot += __shfl_xor_sync(0xFFFFFFFFu, dot, 4);

    __shared__ float sred[32];
    if (l8 == 0) {
        float cs = dot / ((g_an[p] + EPSF) * (g_bn[q] + EPSF));
        sred[grp] = 1.f - cs;
    }
    __syncthreads();
    if (tid < 32) {
        float v = sred[tid];
        #pragma unroll
        for (int m = 16; m >= 1; m >>= 1)
            v += __shfl_xor_sync(0xFFFFFFFFu, v, m);
        if (tid == 0) g_partial[blockIdx.x] = v;
    }
}

__global__ void k_final(float* __restrict__ out) {
    __shared__ float s[512];
    int t = threadIdx.x;
    s[t] = g_partial[t];
    __syncthreads();
    #pragma unroll
    for (int st = 256; st >= 1; st >>= 1) {
        if (t < st) s[t] += s[t + st];
        __syncthreads();
    }
    if (t == 0) out[0] = s[0] / (float)HW;
}

// ---------------- launch ----------------
extern "C" void kernel_launch(void* const* d_in, const int* in_sizes, int n_in,
                              void* d_out, int out_size) {
    const float* a = (const float*)d_in[0];
    const float* b = (const float*)d_in[1];
    float* out = (float*)d_out;

    cudaFuncSetAttribute(k_gemm, cudaFuncAttributeMaxDynamicSharedMemorySize, SMEM_BYTES);

    k_cvt<<<dim3(HW / 32, CCH / 32, 2), dim3(32, 8)>>>(a, b);
    k_finnorm<<<128, 256>>>();
    k_gemm<<<dim3(HW / 128, HW / 128), 128, SMEM_BYTES>>>();
    k_loss<<<HW / 32, 256>>>(a, b);
    k_final<<<1, 512>>>(out);
}

// round 6
// speedup vs baseline: 12.7357x; 1.1052x over previous
#include <cuda_runtime.h>
#include <cuda_fp16.h>
#include <cstdint>

#define HW   16384
#define CCH  256
#define EPSF 1e-8f

// ---------------- scratch (no allocations allowed) ----------------
__device__ float              g_inv_nb[HW];
__device__ float              g_bn[HW];
__device__ float              g_an[HW];
__device__ unsigned long long g_best[HW];
__device__ float              g_partial[512];
__device__ float              g_pnorm[2][4][HW];   // per-64ch-block partial sumsq
__device__ __half             g_ah[HW * CCH];      // fp16, [p][c] K-major, 8MB
__device__ __half             g_bh[HW * CCH];      // fp16, [q][c] K-major, 8MB

// ---------------- helpers ----------------
__device__ __forceinline__ uint32_t smem_to_u32(const void* p) {
    uint32_t a;
    asm("{ .reg .u64 t; cvta.to.shared.u64 t, %1; cvt.u32.u64 %0, t; }" : "=r"(a) : "l"(p));
    return a;
}
__device__ __forceinline__ void cp16(uint32_t dst, const void* src) {
    asm volatile("cp.async.ca.shared.global [%0], [%1], 16;" :: "r"(dst), "l"(src) : "memory");
}
__device__ __forceinline__ void mma_f16(float* d, const uint32_t* a, const uint32_t* b) {
    asm volatile(
        "mma.sync.aligned.m16n8k16.row.col.f32.f16.f16.f32 "
        "{%0,%1,%2,%3}, {%4,%5,%6,%7}, {%8,%9}, {%0,%1,%2,%3};"
        : "+f"(d[0]), "+f"(d[1]), "+f"(d[2]), "+f"(d[3])
        : "r"(a[0]), "r"(a[1]), "r"(a[2]), "r"(a[3]), "r"(b[0]), "r"(b[1]));
}
__device__ __forceinline__ void ldsm4(uint32_t* r, uint32_t addr) {
    asm volatile("ldmatrix.sync.aligned.m8n8.x4.shared.b16 {%0,%1,%2,%3}, [%4];"
                 : "=r"(r[0]), "=r"(r[1]), "=r"(r[2]), "=r"(r[3]) : "r"(addr));
}

// smem: 3 ring buffers of (A 16KB + B 16KB) + inv
static constexpr int BUF_BYTES = 32768;
static constexpr int OFF_INV   = 3 * BUF_BYTES;       // 98304
static constexpr int SMEM_BYTES = OFF_INV + 512;

// ---------------- kernel 0: fp32 [C,HW] -> fp16 [HW,C] transpose + norm partials ----------------
__global__ void k_cvt(const float* __restrict__ a, const float* __restrict__ b) {
    __shared__ float t[64][33];
    __shared__ float ps[8][33];
    const int z = blockIdx.z;
    const float* src = z ? b : a;
    __half*      dst = z ? g_bh : g_ah;
    int p0 = blockIdx.x * 32, c0 = blockIdx.y * 64;
    int tx = threadIdx.x, ty = threadIdx.y;   // 32 x 8

    float ss = 0.f;
    #pragma unroll
    for (int i = 0; i < 8; ++i) {
        float v = src[(size_t)(c0 + ty + i * 8) * HW + p0 + tx];
        t[ty + i * 8][tx] = v;
        ss = fmaf(v, v, ss);
    }
    ps[ty][tx] = ss;
    __syncthreads();

    // half2 stores: thread owns channels (2tx, 2tx+1) for 4 pixels
    #pragma unroll
    for (int i = 0; i < 4; ++i) {
        int pl = ty + i * 8;
        __half2 h = __floats2half2_rn(t[2 * tx][pl], t[2 * tx + 1][pl]);
        *(__half2*)(dst + (size_t)(p0 + pl) * CCH + c0 + 2 * tx) = h;
    }
    if (ty == 0) {
        float s = 0.f;
        #pragma unroll
        for (int j = 0; j < 8; ++j) s += ps[j][tx];
        g_pnorm[z][c0 >> 6][p0 + tx] = s;
    }
}

// ---------------- kernel 1: finish norms + init best ----------------
__global__ void k_finnorm() {
    int idx = blockIdx.x * blockDim.x + threadIdx.x;   // 0..32767
    if (idx < HW) {
        float ss = 0.f;
        #pragma unroll
        for (int cb = 0; cb < 4; ++cb) ss += g_pnorm[1][cb][idx];
        g_inv_nb[idx] = 1.f / (sqrtf(ss + EPSF) + EPSF);
        g_bn[idx]     = sqrtf(ss);
        g_best[idx]   = 0ULL;
    } else {
        int p = idx - HW;
        float ss = 0.f;
        #pragma unroll
        for (int cb = 0; cb < 4; ++cb) ss += g_pnorm[0][cb][p];
        g_an[p] = sqrtf(ss);
    }
}

// ---------------- kernel 2: mma.sync fp16 GEMM (64x64 warp tiles, 3-buf ring) ----------------
__device__ __forceinline__ void load_stage(uint32_t smb, int bufOff,
                                           int bm, int bn, int s, int tid) {
    #pragma unroll
    for (int i = 0; i < 8; ++i) {
        int idx = tid + i * 128;           // 0..1023
        int row = idx >> 3, seg = idx & 7; // seg = 16B (8 fp16) chunk of K64
        uint32_t d = smb + bufOff + row * 128 + ((seg ^ (row & 7)) << 4);
        cp16(d, g_ah + (size_t)(bm + row) * CCH + s * 64 + seg * 8);
    }
    #pragma unroll
    for (int i = 0; i < 8; ++i) {
        int idx = tid + i * 128;
        int row = idx >> 3, seg = idx & 7;
        uint32_t d = smb + bufOff + 16384 + row * 128 + ((seg ^ (row & 7)) << 4);
        cp16(d, g_bh + (size_t)(bn + row) * CCH + s * 64 + seg * 8);
    }
}

__global__ void __launch_bounds__(128, 2)
k_gemm() {
    extern __shared__ __align__(1024) char sm[];
    const uint32_t smb = smem_to_u32(sm);
    const int tid  = threadIdx.x;
    const int lane = tid & 31;
    const int wid  = tid >> 5;    // 0..3
    const int wm   = wid & 1;     // 2 warps along M (64 rows each)
    const int wn   = wid >> 1;    // 2 warps along N (64 cols each)
    const int g    = lane >> 2;   // groupID 0..7
    const int tig  = lane & 3;    // thread-in-group
    const int t8   = lane >> 3;   // ldmatrix tile index 0..3
    const int jr   = lane & 7;    // row within tile

    const int bm = blockIdx.x * 128;   // M fast -> wave shares B tile, A stays in L2
    const int bn = blockIdx.y * 128;

    float* inv_s = (float*)(sm + OFF_INV);
    inv_s[tid] = g_inv_nb[bn + tid];

    // ldmatrix per-lane address invariants
    const uint32_t aRow = (uint32_t)((wm * 64 + (t8 & 1) * 8 + jr) * 128);
    const uint32_t aSel = (uint32_t)(t8 >> 1);
    const uint32_t bRow = (uint32_t)((wn * 64 + (t8 >> 1) * 8 + jr) * 128);
    const uint32_t bSel = (uint32_t)(t8 & 1);
    const uint32_t jrx  = (uint32_t)jr;

    float acc[4][8][4];
    #pragma unroll
    for (int mt = 0; mt < 4; ++mt)
        #pragma unroll
        for (int nt = 0; nt < 8; ++nt)
            #pragma unroll
            for (int c = 0; c < 4; ++c) acc[mt][nt][c] = 0.f;

    // prologue: prefetch stages 0,1 into buffers 0,1
    load_stage(smb, 0 * BUF_BYTES, bm, bn, 0, tid);
    asm volatile("cp.async.commit_group;" ::: "memory");
    load_stage(smb, 1 * BUF_BYTES, bm, bn, 1, tid);
    asm volatile("cp.async.commit_group;" ::: "memory");

    #pragma unroll
    for (int s = 0; s < 4; ++s) {
        asm volatile("cp.async.wait_group 1;" ::: "memory");
        __syncthreads();
        if (s < 2) {
            load_stage(smb, ((s + 2) % 3) * BUF_BYTES, bm, bn, s + 2, tid);
        }
        asm volatile("cp.async.commit_group;" ::: "memory");   // real or empty group

        const uint32_t bufA = smb + (s % 3) * BUF_BYTES + aRow;
        const uint32_t bufB = smb + (s % 3) * BUF_BYTES + 16384 + bRow;

        #pragma unroll
        for (int ks = 0; ks < 4; ++ks) {   // k16 steps within K=64 stage
            const uint32_t aOff = ((((uint32_t)(2 * ks) | aSel) ^ jrx) << 4);
            const uint32_t bOff = ((((uint32_t)(2 * ks) | bSel) ^ jrx) << 4);

            uint32_t afr[4][4], bfr[4][4];
            #pragma unroll
            for (int mt = 0; mt < 4; ++mt) ldsm4(afr[mt], bufA + mt * 2048 + aOff);
            #pragma unroll
            for (int bt = 0; bt < 4; ++bt) ldsm4(bfr[bt], bufB + bt * 2048 + bOff);

            #pragma unroll
            for (int mt = 0; mt < 4; ++mt)
                #pragma unroll
                for (int bt = 0; bt < 4; ++bt) {
                    mma_f16(acc[mt][2 * bt],     afr[mt], bfr[bt]);
                    mma_f16(acc[mt][2 * bt + 1], afr[mt], bfr[bt] + 2);
                }
        }
    }

    // ---- epilogue: scale by 1/nb, per-row argmax, lane reduce, global atomicMax ----
    float invE[8], invO[8];
    #pragma unroll
    for (int nt = 0; nt < 8; ++nt) {
        int c0 = wn * 64 + nt * 8 + 2 * tig;
        invE[nt] = inv_s[c0];
        invO[nt] = inv_s[c0 + 1];
    }

    #pragma unroll
    for (int mt = 0; mt < 4; ++mt) {
        #pragma unroll
        for (int half = 0; half < 2; ++half) {
            float bestv = -3.402823e38f;
            int   bcol  = 0;
            #pragma unroll
            for (int nt = 0; nt < 8; ++nt) {
                int   c0 = wn * 64 + nt * 8 + 2 * tig;
                float v0 = acc[mt][nt][half * 2]     * invE[nt];
                float v1 = acc[mt][nt][half * 2 + 1] * invO[nt];
                if (v0 > bestv) { bestv = v0; bcol = c0; }
                if (v1 > bestv) { bestv = v1; bcol = c0 + 1; }
            }
            unsigned u = __float_as_uint(bestv);
            u = (u & 0x80000000u) ? ~u : (u | 0x80000000u);
            unsigned q = (unsigned)(bn + bcol);
            unsigned long long key =
                ((unsigned long long)u << 32) | (unsigned long long)(0xFFFFFFFFu - q);

            unsigned long long o = __shfl_xor_sync(0xFFFFFFFFu, key, 1);
            if (o > key) key = o;
            o = __shfl_xor_sync(0xFFFFFFFFu, key, 2);
            if (o > key) key = o;

            if (tig == 0) {
                int row = bm + wm * 64 + mt * 16 + g + half * 8;
                atomicMax(&g_best[row], key);
            }
        }
    }
}

// ---------------- kernel 3: fp16 gather dot (coalesced), exact norms ----------------
__global__ void k_loss() {
    const int tid = threadIdx.x;          // 256
    const int grp = tid >> 3;             // 0..31 : pixel slot
    const int l8  = tid & 7;
    const int p   = blockIdx.x * 32 + grp;

    unsigned long long key = g_best[p];
    int q = (int)(0xFFFFFFFFu - (unsigned)(key & 0xFFFFFFFFull));

    // lane handles 32 channels: 4 x uint4 (8 halves each), fully coalesced
    const __half* ap = g_ah + (size_t)p * CCH + l8 * 32;
    const __half* bp = g_bh + (size_t)q * CCH + l8 * 32;
    float dot = 0.f;
    #pragma unroll
    for (int i = 0; i < 4; ++i) {
        uint4 av = *(const uint4*)(ap + i * 8);
        uint4 bv = *(const uint4*)(bp + i * 8);
        const __half2* ah2 = (const __half2*)&av;
        const __half2* bh2 = (const __half2*)&bv;
        #pragma unroll
        for (int j = 0; j < 4; ++j) {
            float2 af = __half22float2(ah2[j]);
            float2 bf = __half22float2(bh2[j]);
            dot = fmaf(af.x, bf.x, dot);
            dot = fmaf(af.y, bf.y, dot);
        }
    }
    dot += __shfl_xor_sync(0xFFFFFFFFu, dot, 1);
    dot += __shfl_xor_sync(0xFFFFFFFFu, dot, 2);
    dot += __shfl_xor_sync(0xFFFFFFFFu, dot, 4);

    __shared__ float sred[32];
    if (l8 == 0) {
        float cs = dot / ((g_an[p] + EPSF) * (g_bn[q] + EPSF));
        sred[grp] = 1.f - cs;
    }
    __syncthreads();
    if (tid < 32) {
        float v = sred[tid];
        #pragma unroll
        for (int m = 16; m >= 1; m >>= 1)
            v += __shfl_xor_sync(0xFFFFFFFFu, v, m);
        if (tid == 0) g_partial[blockIdx.x] = v;
    }
}

__global__ void k_final(float* __restrict__ out) {
    __shared__ float s[512];
    int t = threadIdx.x;
    s[t] = g_partial[t];
    __syncthreads();
    #pragma unroll
    for (int st = 256; st >= 1; st >>= 1) {
        if (t < st) s[t] += s[t + st];
        __syncthreads();
    }
    if (t == 0) out[0] = s[0] / (float)HW;
}

// ---------------- launch ----------------
extern "C" void kernel_launch(void* const* d_in, const int* in_sizes, int n_in,
                              void* d_out, int out_size) {
    const float* a = (const float*)d_in[0];
    const float* b = (const float*)d_in[1];
    float* out = (float*)d_out;

    cudaFuncSetAttribute(k_gemm, cudaFuncAttributeMaxDynamicSharedMemorySize, SMEM_BYTES);

    k_cvt<<<dim3(HW / 32, CCH / 64, 2), dim3(32, 8)>>>(a, b);
    k_finnorm<<<128, 256>>>();
    k_gemm<<<dim3(HW / 128, HW / 128), 128, SMEM_BYTES>>>();
    k_loss<<<HW / 32, 256>>>();
    k_final<<<1, 512>>>(out);
}

// round 7
// speedup vs baseline: 12.9890x; 1.0199x over previous
#include <cuda_runtime.h>
#include <cuda_fp16.h>
#include <cstdint>

#define HW   16384
#define CCH  256
#define EPSF 1e-8f

// ---------------- scratch (no allocations allowed) ----------------
__device__ float              g_inv_nb[HW];
__device__ float              g_bn[HW];
__device__ float              g_an[HW];
__device__ unsigned long long g_best[HW];
__device__ float              g_partial[512];
__device__ __half             g_ah[HW * CCH];      // fp16, [p][c] K-major, 8MB
__device__ __half             g_bh[HW * CCH];      // fp16, [q][c] K-major, 8MB

// ---------------- helpers ----------------
__device__ __forceinline__ uint32_t smem_to_u32(const void* p) {
    uint32_t a;
    asm("{ .reg .u64 t; cvta.to.shared.u64 t, %1; cvt.u32.u64 %0, t; }" : "=r"(a) : "l"(p));
    return a;
}
__device__ __forceinline__ void cp16(uint32_t dst, const void* src) {
    asm volatile("cp.async.ca.shared.global [%0], [%1], 16;" :: "r"(dst), "l"(src) : "memory");
}
// fp16-accumulator MMA: D(f16x2 x2) = A*B + D
__device__ __forceinline__ void mma_f16acc(uint32_t* d, const uint32_t* a, const uint32_t* b) {
    asm volatile(
        "mma.sync.aligned.m16n8k16.row.col.f16.f16.f16.f16 "
        "{%0,%1}, {%2,%3,%4,%5}, {%6,%7}, {%0,%1};"
        : "+r"(d[0]), "+r"(d[1])
        : "r"(a[0]), "r"(a[1]), "r"(a[2]), "r"(a[3]), "r"(b[0]), "r"(b[1]));
}
__device__ __forceinline__ void ldsm4(uint32_t* r, uint32_t addr) {
    asm volatile("ldmatrix.sync.aligned.m8n8.x4.shared.b16 {%0,%1,%2,%3}, [%4];"
                 : "=r"(r[0]), "=r"(r[1]), "=r"(r[2]), "=r"(r[3]) : "r"(addr));
}

// smem: 3 ring buffers of (A 16KB + B 16KB) + inv
static constexpr int BUF_BYTES = 32768;
static constexpr int OFF_INV   = 3 * BUF_BYTES;       // 98304
static constexpr int SMEM_BYTES = OFF_INV + 512;

// ---------------- kernel 0: fused transpose->fp16 + exact norms + init ----------------
// One block per 32-pixel strip, all 256 channels. blockIdx.y selects tensor.
__global__ void k_cvt(const float* __restrict__ a, const float* __restrict__ b) {
    __shared__ float t[32][257];   // [pixel][channel], stride 257 -> conflict-free load
    __shared__ float ps[8][33];
    const int z = blockIdx.y;
    const float* src = z ? b : a;
    __half*      dst = z ? g_bh : g_ah;
    const int p0 = blockIdx.x * 32;
    const int tx = threadIdx.x, ty = threadIdx.y;   // 32 x 8

    float ss = 0.f;
    #pragma unroll
    for (int i = 0; i < 32; ++i) {
        int c = ty + i * 8;
        float v = src[(size_t)c * HW + p0 + tx];
        t[tx][c] = v;
        ss = fmaf(v, v, ss);
    }
    ps[ty][tx] = ss;
    __syncthreads();

    if (ty == 0) {
        float s = 0.f;
        #pragma unroll
        for (int j = 0; j < 8; ++j) s += ps[j][tx];
        int p = p0 + tx;
        if (z) {
            g_inv_nb[p] = 1.f / (sqrtf(s + EPSF) + EPSF);
            g_bn[p]     = sqrtf(s);
            g_best[p]   = 0ULL;
        } else {
            g_an[p] = sqrtf(s);
        }
    }

    // store: warp ty writes pixels p0+ty*4..+3; lane tx builds 16B of 8 channels
    #pragma unroll
    for (int pp = 0; pp < 4; ++pp) {
        int px = ty * 4 + pp;
        int c0 = tx * 8;
        uint32_t w[4];
        #pragma unroll
        for (int j = 0; j < 4; ++j) {
            __half2 h = __floats2half2_rn(t[px][c0 + 2 * j], t[px][c0 + 2 * j + 1]);
            w[j] = *(uint32_t*)&h;
        }
        *(uint4*)(dst + (size_t)(p0 + px) * CCH + c0) = make_uint4(w[0], w[1], w[2], w[3]);
    }
}

// ---------------- kernel 1: mma.sync fp16 GEMM (fp16 accum, 64x64 warp tiles) ----------------
__device__ __forceinline__ void load_stage(uint32_t smb, int bufOff,
                                           int bm, int bn, int s, int tid) {
    #pragma unroll
    for (int i = 0; i < 8; ++i) {
        int idx = tid + i * 128;           // 0..1023
        int row = idx >> 3, seg = idx & 7; // seg = 16B (8 fp16) chunk of K64
        uint32_t d = smb + bufOff + row * 128 + ((seg ^ (row & 7)) << 4);
        cp16(d, g_ah + (size_t)(bm + row) * CCH + s * 64 + seg * 8);
    }
    #pragma unroll
    for (int i = 0; i < 8; ++i) {
        int idx = tid + i * 128;
        int row = idx >> 3, seg = idx & 7;
        uint32_t d = smb + bufOff + 16384 + row * 128 + ((seg ^ (row & 7)) << 4);
        cp16(d, g_bh + (size_t)(bn + row) * CCH + s * 64 + seg * 8);
    }
}

__global__ void __launch_bounds__(128, 2)
k_gemm() {
    extern __shared__ __align__(1024) char sm[];
    const uint32_t smb = smem_to_u32(sm);
    const int tid  = threadIdx.x;
    const int lane = tid & 31;
    const int wid  = tid >> 5;    // 0..3
    const int wm   = wid & 1;     // 2 warps along M (64 rows each)
    const int wn   = wid >> 1;    // 2 warps along N (64 cols each)
    const int g    = lane >> 2;   // groupID 0..7
    const int tig  = lane & 3;    // thread-in-group
    const int t8   = lane >> 3;   // ldmatrix tile index 0..3
    const int jr   = lane & 7;    // row within tile

    const int bm = blockIdx.x * 128;   // M fast -> wave shares B tile, data stays in L2
    const int bn = blockIdx.y * 128;

    float* inv_s = (float*)(sm + OFF_INV);
    inv_s[tid] = g_inv_nb[bn + tid];

    // ldmatrix per-lane address invariants
    const uint32_t aRow = (uint32_t)((wm * 64 + (t8 & 1) * 8 + jr) * 128);
    const uint32_t aSel = (uint32_t)(t8 >> 1);
    const uint32_t bRow = (uint32_t)((wn * 64 + (t8 >> 1) * 8 + jr) * 128);
    const uint32_t bSel = (uint32_t)(t8 & 1);
    const uint32_t jrx  = (uint32_t)jr;

    uint32_t acc[4][8][2];   // fp16x2 accumulators
    #pragma unroll
    for (int mt = 0; mt < 4; ++mt)
        #pragma unroll
        for (int nt = 0; nt < 8; ++nt) { acc[mt][nt][0] = 0u; acc[mt][nt][1] = 0u; }

    // prologue: prefetch stages 0,1 into buffers 0,1
    load_stage(smb, 0 * BUF_BYTES, bm, bn, 0, tid);
    asm volatile("cp.async.commit_group;" ::: "memory");
    load_stage(smb, 1 * BUF_BYTES, bm, bn, 1, tid);
    asm volatile("cp.async.commit_group;" ::: "memory");

    #pragma unroll
    for (int s = 0; s < 4; ++s) {
        asm volatile("cp.async.wait_group 1;" ::: "memory");
        __syncthreads();
        if (s < 2) {
            load_stage(smb, ((s + 2) % 3) * BUF_BYTES, bm, bn, s + 2, tid);
        }
        asm volatile("cp.async.commit_group;" ::: "memory");   // real or empty group

        const uint32_t bufA = smb + (s % 3) * BUF_BYTES + aRow;
        const uint32_t bufB = smb + (s % 3) * BUF_BYTES + 16384 + bRow;

        #pragma unroll
        for (int ks = 0; ks < 4; ++ks) {   // k16 steps within K=64 stage
            const uint32_t aOff = ((((uint32_t)(2 * ks) | aSel) ^ jrx) << 4);
            const uint32_t bOff = ((((uint32_t)(2 * ks) | bSel) ^ jrx) << 4);

            uint32_t afr[4][4], bfr[4][4];
            #pragma unroll
            for (int mt = 0; mt < 4; ++mt) ldsm4(afr[mt], bufA + mt * 2048 + aOff);
            #pragma unroll
            for (int bt = 0; bt < 4; ++bt) ldsm4(bfr[bt], bufB + bt * 2048 + bOff);

            #pragma unroll
            for (int mt = 0; mt < 4; ++mt)
                #pragma unroll
                for (int bt = 0; bt < 4; ++bt) {
                    mma_f16acc(acc[mt][2 * bt],     afr[mt], bfr[bt]);
                    mma_f16acc(acc[mt][2 * bt + 1], afr[mt], bfr[bt] + 2);
                }
        }
    }

    // ---- epilogue: scale by 1/nb, per-row argmax, lane reduce, global atomicMax ----
    float invE[8], invO[8];
    #pragma unroll
    for (int nt = 0; nt < 8; ++nt) {
        int c0 = wn * 64 + nt * 8 + 2 * tig;
        invE[nt] = inv_s[c0];
        invO[nt] = inv_s[c0 + 1];
    }

    #pragma unroll
    for (int mt = 0; mt < 4; ++mt) {
        #pragma unroll
        for (int half = 0; half < 2; ++half) {
            float bestv = -3.402823e38f;
            int   bcol  = 0;
            #pragma unroll
            for (int nt = 0; nt < 8; ++nt) {
                int    c0 = wn * 64 + nt * 8 + 2 * tig;
                float2 f  = __half22float2(*(__half2*)&acc[mt][nt][half]);
                float  v0 = f.x * invE[nt];
                float  v1 = f.y * invO[nt];
                if (v0 > bestv) { bestv = v0; bcol = c0; }
                if (v1 > bestv) { bestv = v1; bcol = c0 + 1; }
            }
            unsigned u = __float_as_uint(bestv);
            u = (u & 0x80000000u) ? ~u : (u | 0x80000000u);
            unsigned q = (unsigned)(bn + bcol);
            unsigned long long key =
                ((unsigned long long)u << 32) | (unsigned long long)(0xFFFFFFFFu - q);

            unsigned long long o = __shfl_xor_sync(0xFFFFFFFFu, key, 1);
            if (o > key) key = o;
            o = __shfl_xor_sync(0xFFFFFFFFu, key, 2);
            if (o > key) key = o;

            if (tig == 0) {
                int row = bm + wm * 64 + mt * 16 + g + half * 8;
                atomicMax(&g_best[row], key);
            }
        }
    }
}

// ---------------- kernel 2: fp16 gather dot (coalesced), exact fp32 cosine ----------------
__global__ void k_loss() {
    const int tid = threadIdx.x;          // 256
    const int grp = tid >> 3;             // 0..31 : pixel slot
    const int l8  = tid & 7;
    const int p   = blockIdx.x * 32 + grp;

    unsigned long long key = g_best[p];
    int q = (int)(0xFFFFFFFFu - (unsigned)(key & 0xFFFFFFFFull));

    const __half* ap = g_ah + (size_t)p * CCH + l8 * 32;
    const __half* bp = g_bh + (size_t)q * CCH + l8 * 32;
    float dot = 0.f;
    #pragma unroll
    for (int i = 0; i < 4; ++i) {
        uint4 av = *(const uint4*)(ap + i * 8);
        uint4 bv = *(const uint4*)(bp + i * 8);
        const __half2* ah2 = (const __half2*)&av;
        const __half2* bh2 = (const __half2*)&bv;
        #pragma unroll
        for (int j = 0; j < 4; ++j) {
            float2 af = __half22float2(ah2[j]);
            float2 bf = __half22float2(bh2[j]);
            dot = fmaf(af.x, bf.x, dot);
            dot = fmaf(af.y, bf.y, dot);
        }
    }
    dot += __shfl_xor_sync(0xFFFFFFFFu, dot, 1);
    dot += __shfl_xor_sync(0xFFFFFFFFu, dot, 2);
    dot += __shfl_xor_sync(0xFFFFFFFFu, dot, 4);

    __shared__ float sred[32];
    if (l8 == 0) {
        float cs = dot / ((g_an[p] + EPSF) * (g_bn[q] + EPSF));
        sred[grp] = 1.f - cs;
    }
    __syncthreads();
    if (tid < 32) {
        float v = sred[tid];
        #pragma unroll
        for (int m = 16; m >= 1; m >>= 1)
            v += __shfl_xor_sync(0xFFFFFFFFu, v, m);
        if (tid == 0) g_partial[blockIdx.x] = v;
    }
}

__global__ void k_final(float* __restrict__ out) {
    __shared__ float s[512];
    int t = threadIdx.x;
    s[t] = g_partial[t];
    __syncthreads();
    #pragma unroll
    for (int st = 256; st >= 1; st >>= 1) {
        if (t < st) s[t] += s[t + st];
        __syncthreads();
    }
    if (t == 0) out[0] = s[0] / (float)HW;
}

// ---------------- launch ----------------
extern "C" void kernel_launch(void* const* d_in, const int* in_sizes, int n_in,
                              void* d_out, int out_size) {
    const float* a = (const float*)d_in[0];
    const float* b = (const float*)d_in[1];
    float* out = (float*)d_out;

    cudaFuncSetAttribute(k_gemm, cudaFuncAttributeMaxDynamicSharedMemorySize, SMEM_BYTES);

    k_cvt<<<dim3(HW / 32, 2), dim3(32, 8)>>>(a, b);
    k_gemm<<<dim3(HW / 128, HW / 128), 128, SMEM_BYTES>>>();
    k_loss<<<HW / 32, 256>>>();
    k_final<<<1, 512>>>(out);
}